// round 7
// baseline (speedup 1.0000x reference)
#include <cuda_runtime.h>
#include <cuda_fp16.h>
#include <cstdint>

#define B_  16
#define T_  1024
#define C_  1024
#define M_  (B_ * T_)   // 16384

#define LO_SCALE 2048.0f
#define LO_INV   (1.0f / 2048.0f)

// ---------------- scratch ----------------
__device__ __half g_xh[M_ * C_];
__device__ __half g_xl[M_ * C_];          // scaled x 2048
__device__ __half g_wk[C_ * C_];
__device__ __half g_wr[C_ * C_];
__device__ __half g_wo[C_ * C_];
__device__ float g_k[M_ * C_];
__device__ float g_r[M_ * C_];
__device__ __half g_sh[M_ * C_];
__device__ __half g_sl[M_ * C_];          // scaled x 2048

// ---------------- helpers ----------------
__device__ __forceinline__ uint32_t smem_u32(const void* p) {
    uint32_t a;
    asm("{ .reg .u64 t; cvta.to.shared.u64 t, %1; cvt.u32.u64 %0, t; }" : "=r"(a) : "l"(p));
    return a;
}
__device__ __forceinline__ void cp_async16(uint32_t s, const void* g) {
    asm volatile("cp.async.cg.shared.global [%0], [%1], 16;" :: "r"(s), "l"(g) : "memory");
}
__device__ __forceinline__ void cp_commit() {
    asm volatile("cp.async.commit_group;" ::: "memory");
}
template<int N> __device__ __forceinline__ void cp_wait() {
    asm volatile("cp.async.wait_group %0;" :: "n"(N) : "memory");
}
__device__ __forceinline__ void ldmatrix4(uint32_t& r0, uint32_t& r1, uint32_t& r2, uint32_t& r3, uint32_t addr) {
    asm volatile("ldmatrix.sync.aligned.m8n8.x4.shared.b16 {%0,%1,%2,%3}, [%4];"
                 : "=r"(r0), "=r"(r1), "=r"(r2), "=r"(r3) : "r"(addr));
}
// fp32-accum HMMA
__device__ __forceinline__ void mma_f32(float& c0, float& c1, float& c2, float& c3,
                                        uint32_t a0, uint32_t a1, uint32_t a2, uint32_t a3,
                                        uint32_t b0, uint32_t b1) {
    asm volatile("mma.sync.aligned.m16n8k16.row.col.f32.f16.f16.f32 "
                 "{%0,%1,%2,%3}, {%4,%5,%6,%7}, {%8,%9}, {%0,%1,%2,%3};"
                 : "+f"(c0), "+f"(c1), "+f"(c2), "+f"(c3)
                 : "r"(a0), "r"(a1), "r"(a2), "r"(a3), "r"(b0), "r"(b1));
}
// fp16-accum HMMA (full-rate)
__device__ __forceinline__ void mma_f16(uint32_t& d0, uint32_t& d1,
                                        uint32_t a0, uint32_t a1, uint32_t a2, uint32_t a3,
                                        uint32_t b0, uint32_t b1) {
    asm volatile("mma.sync.aligned.m16n8k16.row.col.f16.f16.f16.f16 "
                 "{%0,%1}, {%2,%3,%4,%5}, {%6,%7}, {%0,%1};"
                 : "+r"(d0), "+r"(d1)
                 : "r"(a0), "r"(a1), "r"(a2), "r"(a3), "r"(b0), "r"(b1));
}
__device__ __forceinline__ uint32_t sw128(uint32_t o) { return o ^ ((o >> 3) & 0x70); }

// ---------------- fused fp16 2-term GEMM (NT) ----------------
// blockIdx.x < NSPLIT : Out0 = (Ah + Al/2048) @ W0^T ; else Out1 with W1.
#define BM 128
#define BN 128
#define BK 64
#define NCHUNK (C_ / BK)                    // 16
#define TILE_B (128 * 128)                  // 16KB
#define STAGE_BYTES (3 * TILE_B)            // 48KB
#define STAGES 3
#define SMEM_GEMM (STAGES * STAGE_BYTES)    // 144KB

__global__ __launch_bounds__(256, 1)
void gemm_fp16x2(const __half* __restrict__ Ah, const __half* __restrict__ Al,
                 const __half* __restrict__ W0, const __half* __restrict__ W1,
                 float* __restrict__ Out0, float* __restrict__ Out1, int nsplit)
{
    extern __shared__ char smem[];
    const uint32_t sb = smem_u32(smem);
    const int tid = threadIdx.x;
    const int wid = tid >> 5;
    const int lane = tid & 31;

    const bool second = ((int)blockIdx.x >= nsplit);
    const __half* W = second ? W1 : W0;
    float* Out = second ? Out1 : Out0;
    const int bn = (second ? (blockIdx.x - nsplit) : blockIdx.x) * BN;
    const int bm = blockIdx.y * BM;

    const int wm = (wid >> 2) * 64;
    const int wn = (wid & 3) * 32;

    float acc[4][4][4];
    uint32_t acch[4][4][2];
#pragma unroll
    for (int i = 0; i < 4; i++)
#pragma unroll
        for (int j = 0; j < 4; j++) {
#pragma unroll
            for (int c = 0; c < 4; c++) acc[i][j][c] = 0.f;
            acch[i][j][0] = 0u; acch[i][j][1] = 0u;
        }

    auto load_chunk = [&](int ch, int stage) {
        const int k0 = ch * BK;
        const uint32_t base = sb + stage * STAGE_BYTES;
#pragma unroll
        for (int i = 0; i < 4; i++) {
            int q = tid + i * 256;
            int row = q >> 3, c = q & 7;
            uint32_t so = sw128(row * 128 + c * 16);
            cp_async16(base + so, Ah + (size_t)(bm + row) * C_ + k0 + c * 8);
            cp_async16(base + TILE_B + so, Al + (size_t)(bm + row) * C_ + k0 + c * 8);
            cp_async16(base + 2 * TILE_B + so, W + (size_t)(bn + row) * C_ + k0 + c * 8);
        }
    };

    load_chunk(0, 0); cp_commit();
    load_chunk(1, 1); cp_commit();

    const int lrowA = (lane & 7) + ((lane >> 3) & 1) * 8;
    const int lkbA  = ((lane >> 3) >> 1) * 16;
    const int lrowB = (lane & 7) + ((lane >> 3) >> 1) * 8;
    const int lkbB  = ((lane >> 3) & 1) * 16;

    for (int ch = 0; ch < NCHUNK; ch++) {
        if (ch + 2 < NCHUNK) load_chunk(ch + 2, (ch + 2) % STAGES);
        cp_commit();
        cp_wait<2>();
        __syncthreads();

        const uint32_t base = sb + (ch % STAGES) * STAGE_BYTES;

#pragma unroll
        for (int ks = 0; ks < 4; ks++) {
            uint32_t b[2][4];
#pragma unroll
            for (int nt2 = 0; nt2 < 2; nt2++) {
                int r = wn + nt2 * 16 + lrowB;
                ldmatrix4(b[nt2][0], b[nt2][1], b[nt2][2], b[nt2][3],
                          base + 2 * TILE_B + sw128(r * 128 + ks * 32 + lkbB));
            }
            {   // hi pass: fp32 accum
                uint32_t a[4][4];
#pragma unroll
                for (int mt = 0; mt < 4; mt++) {
                    int r = wm + mt * 16 + lrowA;
                    ldmatrix4(a[mt][0], a[mt][1], a[mt][2], a[mt][3],
                              base + sw128(r * 128 + ks * 32 + lkbA));
                }
#pragma unroll
                for (int mt = 0; mt < 4; mt++)
#pragma unroll
                    for (int nt = 0; nt < 4; nt++)
                        mma_f32(acc[mt][nt][0], acc[mt][nt][1], acc[mt][nt][2], acc[mt][nt][3],
                                a[mt][0], a[mt][1], a[mt][2], a[mt][3],
                                b[nt >> 1][(nt & 1) * 2 + 0], b[nt >> 1][(nt & 1) * 2 + 1]);
            }
            {   // lo pass: fp16 accum (Al pre-scaled x2048)
                uint32_t a[4][4];
#pragma unroll
                for (int mt = 0; mt < 4; mt++) {
                    int r = wm + mt * 16 + lrowA;
                    ldmatrix4(a[mt][0], a[mt][1], a[mt][2], a[mt][3],
                              base + TILE_B + sw128(r * 128 + ks * 32 + lkbA));
                }
#pragma unroll
                for (int mt = 0; mt < 4; mt++)
#pragma unroll
                    for (int nt = 0; nt < 4; nt++)
                        mma_f16(acch[mt][nt][0], acch[mt][nt][1],
                                a[mt][0], a[mt][1], a[mt][2], a[mt][3],
                                b[nt >> 1][(nt & 1) * 2 + 0], b[nt >> 1][(nt & 1) * 2 + 1]);
            }
        }
        __syncthreads();
    }

    // epilogue: merge lo (x 1/2048) into fp32 acc, store
#pragma unroll
    for (int mt = 0; mt < 4; mt++) {
        int row0 = bm + wm + mt * 16 + (lane >> 2);
#pragma unroll
        for (int nt = 0; nt < 4; nt++) {
            float2 l01 = __half22float2(*(__half2*)&acch[mt][nt][0]);
            float2 l23 = __half22float2(*(__half2*)&acch[mt][nt][1]);
            float r0 = fmaf(l01.x, LO_INV, acc[mt][nt][0]);
            float r1 = fmaf(l01.y, LO_INV, acc[mt][nt][1]);
            float r2 = fmaf(l23.x, LO_INV, acc[mt][nt][2]);
            float r3 = fmaf(l23.y, LO_INV, acc[mt][nt][3]);
            int col = bn + wn + nt * 8 + (lane & 3) * 2;
            *(float2*)(Out + (size_t)row0 * C_ + col)       = make_float2(r0, r1);
            *(float2*)(Out + (size_t)(row0 + 8) * C_ + col) = make_float2(r2, r3);
        }
    }
}

// ---------------- fp32 -> fp16 hi/lo split (lo scaled x2048) ----------------
__global__ __launch_bounds__(256)
void split_fp16(const float* __restrict__ in, __half* __restrict__ hi,
                __half* __restrict__ lo, int n4)
{
    int i = blockIdx.x * blockDim.x + threadIdx.x;
    if (i >= n4) return;
    float4 v = ((const float4*)in)[i];
    __half h0 = __float2half_rn(v.x), h1 = __float2half_rn(v.y);
    __half h2 = __float2half_rn(v.z), h3 = __float2half_rn(v.w);
    __half2 hp0{h0, h1}, hp1{h2, h3};
    __half2 lp0{__float2half_rn((v.x - __half2float(h0)) * LO_SCALE),
                __float2half_rn((v.y - __half2float(h1)) * LO_SCALE)};
    __half2 lp1{__float2half_rn((v.z - __half2float(h2)) * LO_SCALE),
                __float2half_rn((v.w - __half2float(h3)) * LO_SCALE)};
    ((__half2*)hi)[i * 2 + 0] = hp0;
    ((__half2*)hi)[i * 2 + 1] = hp1;
    ((__half2*)lo)[i * 2 + 0] = lp0;
    ((__half2*)lo)[i * 2 + 1] = lp1;
}

__global__ __launch_bounds__(256)
void conv_fp16(const float* __restrict__ in, __half* __restrict__ out, int n4)
{
    int i = blockIdx.x * blockDim.x + threadIdx.x;
    if (i >= n4) return;
    float4 v = ((const float4*)in)[i];
    __half2 p0{__float2half_rn(v.x), __float2half_rn(v.y)};
    __half2 p1{__float2half_rn(v.z), __float2half_rn(v.w)};
    ((__half2*)out)[i * 2 + 0] = p0;
    ((__half2*)out)[i * 2 + 1] = p1;
}

// ---------------- WKV scan ----------------
#define PF 8
__global__ __launch_bounds__(128)
void wkv_scan_kernel(const float* __restrict__ time_decay,
                     const float* __restrict__ time_first)
{
    const int gid = blockIdx.x * blockDim.x + threadIdx.x;
    const int b = gid >> 10;
    const int c = gid & (C_ - 1);

    const float w = -__expf(time_decay[c]);
    const float u = time_first[c];

    float a = 0.f, bden = 0.f, pp = -1e38f;

    const float* kp = g_k + (size_t)b * T_ * C_ + c;
    const float* rp = g_r + (size_t)b * T_ * C_ + c;
    __half* shp = g_sh + (size_t)b * T_ * C_ + c;
    __half* slp = g_sl + (size_t)b * T_ * C_ + c;

    float kbuf[PF], rbuf[PF];
#pragma unroll
    for (int i = 0; i < PF; i++) {
        kbuf[i] = kp[(size_t)i * C_];
        rbuf[i] = rp[(size_t)i * C_];
    }

#pragma unroll 8
    for (int t = 0; t < T_; t++) {
        const float kt = kbuf[t & (PF - 1)];
        const float rt = rbuf[t & (PF - 1)];
        if (t + PF < T_) {
            kbuf[t & (PF - 1)] = kp[(size_t)(t + PF) * C_];
            rbuf[t & (PF - 1)] = rp[(size_t)(t + PF) * C_];
        }
        const float vt = rt;

        float ww = u + kt;
        float d  = pp - ww;
        float e  = __expf(-fabsf(d));
        float e1 = (d >= 0.f) ? 1.f : e;
        float e2 = (d >= 0.f) ? e : 1.f;
        float y  = __fdividef(e1 * a + e2 * vt, e1 * bden + e2);

        float ww2 = pp + w;
        float d2  = ww2 - kt;
        float eb  = __expf(-fabsf(d2));
        float e1b = (d2 >= 0.f) ? 1.f : eb;
        float e2b = (d2 >= 0.f) ? eb : 1.f;
        a    = e1b * a + e2b * vt;
        bden = e1b * bden + e2b;
        pp   = fmaxf(ww2, kt);

        float sig = __fdividef(1.f, 1.f + __expf(-rt));
        float s = sig * y;
        __half h = __float2half_rn(s);
        shp[(size_t)t * C_] = h;
        slp[(size_t)t * C_] = __float2half_rn((s - __half2float(h)) * LO_SCALE);
    }
}

// ---------------- launch ----------------
extern "C" void kernel_launch(void* const* d_in, const int* in_sizes, int n_in,
                              void* d_out, int out_size)
{
    const float* x  = (const float*)d_in[0];
    const float* Wk = (const float*)d_in[1];
    const float* Wr = (const float*)d_in[2];
    const float* Wo = (const float*)d_in[3];
    const float* td = (const float*)d_in[4];
    const float* tf = (const float*)d_in[5];
    float* out = (float*)d_out;

    __half *xh, *xl, *wk, *wr, *wo, *sh, *sl;
    float *gk, *gr;
    cudaGetSymbolAddress((void**)&xh, g_xh); cudaGetSymbolAddress((void**)&xl, g_xl);
    cudaGetSymbolAddress((void**)&wk, g_wk); cudaGetSymbolAddress((void**)&wr, g_wr);
    cudaGetSymbolAddress((void**)&wo, g_wo);
    cudaGetSymbolAddress((void**)&sh, g_sh); cudaGetSymbolAddress((void**)&sl, g_sl);
    cudaGetSymbolAddress((void**)&gk, g_k);  cudaGetSymbolAddress((void**)&gr, g_r);

    cudaFuncSetAttribute(gemm_fp16x2, cudaFuncAttributeMaxDynamicSharedMemorySize, SMEM_GEMM);

    split_fp16<<<(M_ * C_ / 4 + 255) / 256, 256>>>(x, xh, xl, M_ * C_ / 4);
    conv_fp16<<<(C_ * C_ / 4 + 255) / 256, 256>>>(Wk, wk, C_ * C_ / 4);
    conv_fp16<<<(C_ * C_ / 4 + 255) / 256, 256>>>(Wr, wr, C_ * C_ / 4);
    conv_fp16<<<(C_ * C_ / 4 + 255) / 256, 256>>>(Wo, wo, C_ * C_ / 4);

    dim3 grid_kr(2 * (C_ / BN), M_ / BM);   // (16, 128) fused k + r
    gemm_fp16x2<<<grid_kr, 256, SMEM_GEMM>>>(xh, xl, wk, wr, gk, gr, C_ / BN);
    wkv_scan_kernel<<<(B_ * C_) / 128, 128>>>(td, tf);
    dim3 grid_o(C_ / BN, M_ / BM);          // (8, 128)
    gemm_fp16x2<<<grid_o, 256, SMEM_GEMM>>>(sh, sl, wo, wo, out, out, C_ / BN);
}

// round 8
// speedup vs baseline: 1.1177x; 1.1177x over previous
#include <cuda_runtime.h>
#include <cuda_fp16.h>
#include <cstdint>

#define B_  16
#define T_  1024
#define C_  1024
#define M_  (B_ * T_)   // 16384

// ---------------- scratch ----------------
__device__ __half g_xh[M_ * C_];
__device__ __half g_xl[M_ * C_];
__device__ __half g_wk[C_ * C_];
__device__ __half g_wr[C_ * C_];
__device__ __half g_wo[C_ * C_];
__device__ float g_k[M_ * C_];
__device__ float g_r[M_ * C_];
__device__ __half g_sh[M_ * C_];
__device__ __half g_sl[M_ * C_];

// ---------------- helpers ----------------
__device__ __forceinline__ uint32_t smem_u32(const void* p) {
    uint32_t a;
    asm("{ .reg .u64 t; cvta.to.shared.u64 t, %1; cvt.u32.u64 %0, t; }" : "=r"(a) : "l"(p));
    return a;
}
__device__ __forceinline__ void cp_async16(uint32_t s, const void* g) {
    asm volatile("cp.async.cg.shared.global [%0], [%1], 16;" :: "r"(s), "l"(g) : "memory");
}
__device__ __forceinline__ void cp_commit() {
    asm volatile("cp.async.commit_group;" ::: "memory");
}
template<int N> __device__ __forceinline__ void cp_wait() {
    asm volatile("cp.async.wait_group %0;" :: "n"(N) : "memory");
}
__device__ __forceinline__ void ldmatrix4(uint32_t& r0, uint32_t& r1, uint32_t& r2, uint32_t& r3, uint32_t addr) {
    asm volatile("ldmatrix.sync.aligned.m8n8.x4.shared.b16 {%0,%1,%2,%3}, [%4];"
                 : "=r"(r0), "=r"(r1), "=r"(r2), "=r"(r3) : "r"(addr));
}
__device__ __forceinline__ void mma16816(float& c0, float& c1, float& c2, float& c3,
                                         uint32_t a0, uint32_t a1, uint32_t a2, uint32_t a3,
                                         uint32_t b0, uint32_t b1) {
    asm volatile("mma.sync.aligned.m16n8k16.row.col.f32.f16.f16.f32 "
                 "{%0,%1,%2,%3}, {%4,%5,%6,%7}, {%8,%9}, {%0,%1,%2,%3};"
                 : "+f"(c0), "+f"(c1), "+f"(c2), "+f"(c3)
                 : "r"(a0), "r"(a1), "r"(a2), "r"(a3), "r"(b0), "r"(b1));
}
__device__ __forceinline__ uint32_t sw128(uint32_t o) { return o ^ ((o >> 3) & 0x70); }

// ---------------- fp16 2-term GEMM (NT), W-shared fused passes (R5 config) ----------------
#define BM 128
#define BN 128
#define BK 64
#define NCHUNK (C_ / BK)                    // 16
#define TILE_B (128 * 128)                  // 16KB
#define STAGE_BYTES (3 * TILE_B)            // 48KB
#define SMEM_GEMM (2 * STAGE_BYTES)         // 96KB, 2 stages

__global__ __launch_bounds__(256, 2)
void gemm_fp16x2(const __half* __restrict__ Ah, const __half* __restrict__ Al,
                 const __half* __restrict__ W, float* __restrict__ Out)
{
    extern __shared__ char smem[];
    const uint32_t sb = smem_u32(smem);
    const int tid = threadIdx.x;
    const int wid = tid >> 5;
    const int lane = tid & 31;
    const int bm = blockIdx.y * BM;
    const int bn = blockIdx.x * BN;

    const int wm = (wid >> 2) * 64;
    const int wn = (wid & 3) * 32;

    float acc[4][4][4];
#pragma unroll
    for (int i = 0; i < 4; i++)
#pragma unroll
        for (int j = 0; j < 4; j++)
#pragma unroll
            for (int c = 0; c < 4; c++) acc[i][j][c] = 0.f;

    auto load_chunk = [&](int ch, int stage) {
        const int k0 = ch * BK;
        const uint32_t base = sb + stage * STAGE_BYTES;
#pragma unroll
        for (int i = 0; i < 4; i++) {
            int q = tid + i * 256;
            int row = q >> 3, c = q & 7;
            uint32_t so = sw128(row * 128 + c * 16);
            cp_async16(base + so, Ah + (size_t)(bm + row) * C_ + k0 + c * 8);
            cp_async16(base + TILE_B + so, Al + (size_t)(bm + row) * C_ + k0 + c * 8);
            cp_async16(base + 2 * TILE_B + so, W + (size_t)(bn + row) * C_ + k0 + c * 8);
        }
    };

    load_chunk(0, 0);
    cp_commit();

    const int lrowA = (lane & 7) + ((lane >> 3) & 1) * 8;
    const int lkbA  = ((lane >> 3) >> 1) * 16;
    const int lrowB = (lane & 7) + ((lane >> 3) >> 1) * 8;
    const int lkbB  = ((lane >> 3) & 1) * 16;

    for (int ch = 0; ch < NCHUNK; ch++) {
        if (ch + 1 < NCHUNK) load_chunk(ch + 1, (ch + 1) & 1);
        cp_commit();
        cp_wait<1>();
        __syncthreads();

        const uint32_t base = sb + (ch & 1) * STAGE_BYTES;

#pragma unroll
        for (int ks = 0; ks < 4; ks++) {
            uint32_t b[2][4];
#pragma unroll
            for (int nt2 = 0; nt2 < 2; nt2++) {
                int r = wn + nt2 * 16 + lrowB;
                ldmatrix4(b[nt2][0], b[nt2][1], b[nt2][2], b[nt2][3],
                          base + 2 * TILE_B + sw128(r * 128 + ks * 32 + lkbB));
            }
            {   // hi pass
                uint32_t a[4][4];
#pragma unroll
                for (int mt = 0; mt < 4; mt++) {
                    int r = wm + mt * 16 + lrowA;
                    ldmatrix4(a[mt][0], a[mt][1], a[mt][2], a[mt][3],
                              base + sw128(r * 128 + ks * 32 + lkbA));
                }
#pragma unroll
                for (int mt = 0; mt < 4; mt++)
#pragma unroll
                    for (int nt = 0; nt < 4; nt++)
                        mma16816(acc[mt][nt][0], acc[mt][nt][1], acc[mt][nt][2], acc[mt][nt][3],
                                 a[mt][0], a[mt][1], a[mt][2], a[mt][3],
                                 b[nt >> 1][(nt & 1) * 2 + 0], b[nt >> 1][(nt & 1) * 2 + 1]);
            }
            {   // lo pass
                uint32_t a[4][4];
#pragma unroll
                for (int mt = 0; mt < 4; mt++) {
                    int r = wm + mt * 16 + lrowA;
                    ldmatrix4(a[mt][0], a[mt][1], a[mt][2], a[mt][3],
                              base + TILE_B + sw128(r * 128 + ks * 32 + lkbA));
                }
#pragma unroll
                for (int mt = 0; mt < 4; mt++)
#pragma unroll
                    for (int nt = 0; nt < 4; nt++)
                        mma16816(acc[mt][nt][0], acc[mt][nt][1], acc[mt][nt][2], acc[mt][nt][3],
                                 a[mt][0], a[mt][1], a[mt][2], a[mt][3],
                                 b[nt >> 1][(nt & 1) * 2 + 0], b[nt >> 1][(nt & 1) * 2 + 1]);
            }
        }
        __syncthreads();
    }

#pragma unroll
    for (int mt = 0; mt < 4; mt++) {
        int row0 = bm + wm + mt * 16 + (lane >> 2);
#pragma unroll
        for (int nt = 0; nt < 4; nt++) {
            int col = bn + wn + nt * 8 + (lane & 3) * 2;
            float2* p0 = (float2*)(Out + (size_t)row0 * C_ + col);
            float2* p1 = (float2*)(Out + (size_t)(row0 + 8) * C_ + col);
            *p0 = make_float2(acc[mt][nt][0], acc[mt][nt][1]);
            *p1 = make_float2(acc[mt][nt][2], acc[mt][nt][3]);
        }
    }
}

// ---------------- fp32 -> fp16 hi/lo split ----------------
__global__ __launch_bounds__(256)
void split_fp16(const float* __restrict__ in, __half* __restrict__ hi,
                __half* __restrict__ lo, int n4)
{
    int i = blockIdx.x * blockDim.x + threadIdx.x;
    if (i >= n4) return;
    float4 v = ((const float4*)in)[i];
    __half h0 = __float2half_rn(v.x), h1 = __float2half_rn(v.y);
    __half h2 = __float2half_rn(v.z), h3 = __float2half_rn(v.w);
    __half2 hp0{h0, h1}, hp1{h2, h3};
    __half2 lp0{__float2half_rn(v.x - __half2float(h0)), __float2half_rn(v.y - __half2float(h1))};
    __half2 lp1{__float2half_rn(v.z - __half2float(h2)), __float2half_rn(v.w - __half2float(h3))};
    ((__half2*)hi)[i * 2 + 0] = hp0;
    ((__half2*)hi)[i * 2 + 1] = hp1;
    ((__half2*)lo)[i * 2 + 0] = lp0;
    ((__half2*)lo)[i * 2 + 1] = lp1;
}

// all 3 weight conversions in one launch
__global__ __launch_bounds__(256)
void conv_fp16x3(const float* __restrict__ i0, const float* __restrict__ i1,
                 const float* __restrict__ i2, __half* __restrict__ o0,
                 __half* __restrict__ o1, __half* __restrict__ o2, int n4each)
{
    int i = blockIdx.x * blockDim.x + threadIdx.x;
    int which = i / n4each;
    int j = i - which * n4each;
    const float* in = (which == 0) ? i0 : (which == 1) ? i1 : i2;
    __half* out = (which == 0) ? o0 : (which == 1) ? o1 : o2;
    float4 v = ((const float4*)in)[j];
    __half2 p0{__float2half_rn(v.x), __float2half_rn(v.y)};
    __half2 p1{__float2half_rn(v.z), __float2half_rn(v.w)};
    ((__half2*)out)[j * 2 + 0] = p0;
    ((__half2*)out)[j * 2 + 1] = p1;
}

// ---------------- segment-parallel WKV scan ----------------
// Block = 32 channels x 8 segments (256 threads). T split into 8 segments of 128.
// Phase 1: zero-init state-only scan per segment. Phase 2: log-space prefix merge
// across segments (pass-through coefficient exp(L*w) is data-independent).
// Phase 3: re-scan with correct incoming state, emit sh/sl.
#define SEG 8
#define LSEG (T_ / SEG)   // 128

__global__ __launch_bounds__(256)
void wkv_scan_seg(const float* __restrict__ time_decay,
                  const float* __restrict__ time_first)
{
    __shared__ float s_a[SEG][32], s_b[SEG][32], s_p[SEG][32];

    const int lane = threadIdx.x & 31;
    const int seg  = threadIdx.x >> 5;
    const int b  = blockIdx.x >> 5;                    // 32 blocks per batch (C_/32)
    const int c  = ((blockIdx.x & 31) << 5) + lane;

    const float w = -__expf(time_decay[c]);
    const float u = time_first[c];

    const size_t off = ((size_t)b * T_ + (size_t)seg * LSEG) * C_ + c;
    const float* kp = g_k + off;
    const float* rp = g_r + off;

    // ---- phase 1: local scan, zero init, state only ----
    float a = 0.f, bd = 0.f, pp = -1e38f;
#pragma unroll 4
    for (int t = 0; t < LSEG; t++) {
        const float kt = kp[(size_t)t * C_];
        const float vt = rp[(size_t)t * C_];
        float ww2 = pp + w;
        float d2  = ww2 - kt;
        float eb  = __expf(-fabsf(d2));
        float e1b = (d2 >= 0.f) ? 1.f : eb;
        float e2b = (d2 >= 0.f) ? eb : 1.f;
        a  = e1b * a + e2b * vt;
        bd = e1b * bd + e2b;
        pp = fmaxf(ww2, kt);
    }
    s_a[seg][lane] = a; s_b[seg][lane] = bd; s_p[seg][lane] = pp;
    __syncthreads();

    // ---- phase 2: prefix over segments 0..seg-1 ----
    float a0 = 0.f, b0 = 0.f, p0 = -1e38f;
    const float Lw = (float)LSEG * w;
    for (int j = 0; j < seg; j++) {
        float aj = s_a[j][lane], bj = s_b[j][lane], pj = s_p[j][lane];
        float pd = p0 + Lw;
        float pn = fmaxf(pd, pj);
        float ea = __expf(pd - pn);
        float ej = __expf(pj - pn);
        a0 = ea * a0 + ej * aj;
        b0 = ea * b0 + ej * bj;
        p0 = pn;
    }

    // ---- phase 3: re-scan with incoming state, emit outputs ----
    a = a0; bd = b0; pp = p0;
    __half* shp = g_sh + off;
    __half* slp = g_sl + off;
#pragma unroll 4
    for (int t = 0; t < LSEG; t++) {
        const float kt = kp[(size_t)t * C_];
        const float rt = rp[(size_t)t * C_];
        const float vt = rt;

        float ww = u + kt;
        float d  = pp - ww;
        float e  = __expf(-fabsf(d));
        float e1 = (d >= 0.f) ? 1.f : e;
        float e2 = (d >= 0.f) ? e : 1.f;
        float y  = __fdividef(e1 * a + e2 * vt, e1 * bd + e2);

        float ww2 = pp + w;
        float d2  = ww2 - kt;
        float ebv = __expf(-fabsf(d2));
        float e1b = (d2 >= 0.f) ? 1.f : ebv;
        float e2b = (d2 >= 0.f) ? ebv : 1.f;
        a  = e1b * a + e2b * vt;
        bd = e1b * bd + e2b;
        pp = fmaxf(ww2, kt);

        float sig = __fdividef(1.f, 1.f + __expf(-rt));
        float s = sig * y;
        __half h = __float2half_rn(s);
        shp[(size_t)t * C_] = h;
        slp[(size_t)t * C_] = __float2half_rn(s - __half2float(h));
    }
}

// ---------------- launch ----------------
extern "C" void kernel_launch(void* const* d_in, const int* in_sizes, int n_in,
                              void* d_out, int out_size)
{
    const float* x  = (const float*)d_in[0];
    const float* Wk = (const float*)d_in[1];
    const float* Wr = (const float*)d_in[2];
    const float* Wo = (const float*)d_in[3];
    const float* td = (const float*)d_in[4];
    const float* tf = (const float*)d_in[5];
    float* out = (float*)d_out;

    __half *xh, *xl, *wk, *wr, *wo, *sh, *sl;
    float *gk, *gr;
    cudaGetSymbolAddress((void**)&xh, g_xh); cudaGetSymbolAddress((void**)&xl, g_xl);
    cudaGetSymbolAddress((void**)&wk, g_wk); cudaGetSymbolAddress((void**)&wr, g_wr);
    cudaGetSymbolAddress((void**)&wo, g_wo);
    cudaGetSymbolAddress((void**)&sh, g_sh); cudaGetSymbolAddress((void**)&sl, g_sl);
    cudaGetSymbolAddress((void**)&gk, g_k);  cudaGetSymbolAddress((void**)&gr, g_r);

    cudaFuncSetAttribute(gemm_fp16x2, cudaFuncAttributeMaxDynamicSharedMemorySize, SMEM_GEMM);

    split_fp16<<<(M_ * C_ / 4 + 255) / 256, 256>>>(x, xh, xl, M_ * C_ / 4);
    conv_fp16x3<<<(3 * C_ * C_ / 4 + 255) / 256, 256>>>(Wk, Wr, Wo, wk, wr, wo, C_ * C_ / 4);

    dim3 grid(C_ / BN, M_ / BM);   // (8, 128)
    gemm_fp16x2<<<grid, 256, SMEM_GEMM>>>(xh, xl, wk, gk);
    gemm_fp16x2<<<grid, 256, SMEM_GEMM>>>(xh, xl, wr, gr);
    wkv_scan_seg<<<(B_ * C_) / 32, 256>>>(td, tf);
    gemm_fp16x2<<<grid, 256, SMEM_GEMM>>>(sh, sl, wo, out);
}

// round 12
// speedup vs baseline: 1.2560x; 1.1237x over previous
#include <cuda_runtime.h>
#include <cuda_fp16.h>
#include <cstdint>

#define B_  16
#define T_  1024
#define C_  1024
#define M_  (B_ * T_)   // 16384

// ---------------- scratch ----------------
__device__ __half g_xh[M_ * C_];
__device__ __half g_xl[M_ * C_];
__device__ __half g_wk[C_ * C_];
__device__ __half g_wr[C_ * C_];
__device__ __half g_wo[C_ * C_];
__device__ float g_k[M_ * C_];
__device__ float g_r[M_ * C_];
__device__ __half g_sh[M_ * C_];

// ---------------- helpers ----------------
__device__ __forceinline__ uint32_t smem_u32(const void* p) {
    uint32_t a;
    asm("{ .reg .u64 t; cvta.to.shared.u64 t, %1; cvt.u32.u64 %0, t; }" : "=r"(a) : "l"(p));
    return a;
}
__device__ __forceinline__ void cp_async16(uint32_t s, const void* g) {
    asm volatile("cp.async.cg.shared.global [%0], [%1], 16;" :: "r"(s), "l"(g) : "memory");
}
__device__ __forceinline__ void cp_commit() {
    asm volatile("cp.async.commit_group;" ::: "memory");
}
template<int N> __device__ __forceinline__ void cp_wait() {
    asm volatile("cp.async.wait_group %0;" :: "n"(N) : "memory");
}
__device__ __forceinline__ void ldmatrix4(uint32_t& r0, uint32_t& r1, uint32_t& r2, uint32_t& r3, uint32_t addr) {
    asm volatile("ldmatrix.sync.aligned.m8n8.x4.shared.b16 {%0,%1,%2,%3}, [%4];"
                 : "=r"(r0), "=r"(r1), "=r"(r2), "=r"(r3) : "r"(addr));
}
__device__ __forceinline__ void mma16816(float& c0, float& c1, float& c2, float& c3,
                                         uint32_t a0, uint32_t a1, uint32_t a2, uint32_t a3,
                                         uint32_t b0, uint32_t b1) {
    asm volatile("mma.sync.aligned.m16n8k16.row.col.f32.f16.f16.f32 "
                 "{%0,%1,%2,%3}, {%4,%5,%6,%7}, {%8,%9}, {%0,%1,%2,%3};"
                 : "+f"(c0), "+f"(c1), "+f"(c2), "+f"(c3)
                 : "r"(a0), "r"(a1), "r"(a2), "r"(a3), "r"(b0), "r"(b1));
}
__device__ __forceinline__ uint32_t sw128(uint32_t o) { return o ^ ((o >> 3) & 0x70); }

#define BM 128
#define BN 128
#define BK 64
#define NCHUNK (C_ / BK)                    // 16
#define TILE_B (128 * 128)                  // 16KB

// ---------------- fp16 2-term GEMM (k/r; R5/R8 config, unchanged) ----------------
#define STAGE2_BYTES (3 * TILE_B)            // 48KB
#define SMEM_GEMM2 (2 * STAGE2_BYTES)        // 96KB

__global__ __launch_bounds__(256, 2)
void gemm_fp16x2(const __half* __restrict__ Ah, const __half* __restrict__ Al,
                 const __half* __restrict__ W, float* __restrict__ Out)
{
    extern __shared__ char smem[];
    const uint32_t sb = smem_u32(smem);
    const int tid = threadIdx.x;
    const int wid = tid >> 5;
    const int lane = tid & 31;
    const int bm = blockIdx.y * BM;
    const int bn = blockIdx.x * BN;

    const int wm = (wid >> 2) * 64;
    const int wn = (wid & 3) * 32;

    float acc[4][4][4];
#pragma unroll
    for (int i = 0; i < 4; i++)
#pragma unroll
        for (int j = 0; j < 4; j++)
#pragma unroll
            for (int c = 0; c < 4; c++) acc[i][j][c] = 0.f;

    auto load_chunk = [&](int ch, int stage) {
        const int k0 = ch * BK;
        const uint32_t base = sb + stage * STAGE2_BYTES;
#pragma unroll
        for (int i = 0; i < 4; i++) {
            int q = tid + i * 256;
            int row = q >> 3, c = q & 7;
            uint32_t so = sw128(row * 128 + c * 16);
            cp_async16(base + so, Ah + (size_t)(bm + row) * C_ + k0 + c * 8);
            cp_async16(base + TILE_B + so, Al + (size_t)(bm + row) * C_ + k0 + c * 8);
            cp_async16(base + 2 * TILE_B + so, W + (size_t)(bn + row) * C_ + k0 + c * 8);
        }
    };

    load_chunk(0, 0);
    cp_commit();

    const int lrowA = (lane & 7) + ((lane >> 3) & 1) * 8;
    const int lkbA  = ((lane >> 3) >> 1) * 16;
    const int lrowB = (lane & 7) + ((lane >> 3) >> 1) * 8;
    const int lkbB  = ((lane >> 3) & 1) * 16;

    for (int ch = 0; ch < NCHUNK; ch++) {
        if (ch + 1 < NCHUNK) load_chunk(ch + 1, (ch + 1) & 1);
        cp_commit();
        cp_wait<1>();
        __syncthreads();

        const uint32_t base = sb + (ch & 1) * STAGE2_BYTES;

#pragma unroll
        for (int ks = 0; ks < 4; ks++) {
            uint32_t b[2][4];
#pragma unroll
            for (int nt2 = 0; nt2 < 2; nt2++) {
                int r = wn + nt2 * 16 + lrowB;
                ldmatrix4(b[nt2][0], b[nt2][1], b[nt2][2], b[nt2][3],
                          base + 2 * TILE_B + sw128(r * 128 + ks * 32 + lkbB));
            }
            {
                uint32_t a[4][4];
#pragma unroll
                for (int mt = 0; mt < 4; mt++) {
                    int r = wm + mt * 16 + lrowA;
                    ldmatrix4(a[mt][0], a[mt][1], a[mt][2], a[mt][3],
                              base + sw128(r * 128 + ks * 32 + lkbA));
                }
#pragma unroll
                for (int mt = 0; mt < 4; mt++)
#pragma unroll
                    for (int nt = 0; nt < 4; nt++)
                        mma16816(acc[mt][nt][0], acc[mt][nt][1], acc[mt][nt][2], acc[mt][nt][3],
                                 a[mt][0], a[mt][1], a[mt][2], a[mt][3],
                                 b[nt >> 1][(nt & 1) * 2 + 0], b[nt >> 1][(nt & 1) * 2 + 1]);
            }
            {
                uint32_t a[4][4];
#pragma unroll
                for (int mt = 0; mt < 4; mt++) {
                    int r = wm + mt * 16 + lrowA;
                    ldmatrix4(a[mt][0], a[mt][1], a[mt][2], a[mt][3],
                              base + TILE_B + sw128(r * 128 + ks * 32 + lkbA));
                }
#pragma unroll
                for (int mt = 0; mt < 4; mt++)
#pragma unroll
                    for (int nt = 0; nt < 4; nt++)
                        mma16816(acc[mt][nt][0], acc[mt][nt][1], acc[mt][nt][2], acc[mt][nt][3],
                                 a[mt][0], a[mt][1], a[mt][2], a[mt][3],
                                 b[nt >> 1][(nt & 1) * 2 + 0], b[nt >> 1][(nt & 1) * 2 + 1]);
            }
        }
        __syncthreads();
    }

#pragma unroll
    for (int mt = 0; mt < 4; mt++) {
        int row0 = bm + wm + mt * 16 + (lane >> 2);
#pragma unroll
        for (int nt = 0; nt < 4; nt++) {
            int col = bn + wn + nt * 8 + (lane & 3) * 2;
            *(float2*)(Out + (size_t)row0 * C_ + col)       = make_float2(acc[mt][nt][0], acc[mt][nt][1]);
            *(float2*)(Out + (size_t)(row0 + 8) * C_ + col) = make_float2(acc[mt][nt][2], acc[mt][nt][3]);
        }
    }
}

// ---------------- fp16 single-term GEMM (out = s @ Wo^T), 3-stage, FIXED waits ----------------
#define STAGE1_BYTES (2 * TILE_B)            // 32KB
#define STAGES1 3
#define SMEM_GEMM1 (STAGES1 * STAGE1_BYTES)  // 96KB

__global__ __launch_bounds__(256, 2)
void gemm_fp16x1(const __half* __restrict__ A, const __half* __restrict__ W,
                 float* __restrict__ Out)
{
    extern __shared__ char smem[];
    const uint32_t sb = smem_u32(smem);
    const int tid = threadIdx.x;
    const int wid = tid >> 5;
    const int lane = tid & 31;
    const int bm = blockIdx.y * BM;
    const int bn = blockIdx.x * BN;

    const int wm = (wid >> 2) * 64;
    const int wn = (wid & 3) * 32;

    float acc[4][4][4];
#pragma unroll
    for (int i = 0; i < 4; i++)
#pragma unroll
        for (int j = 0; j < 4; j++)
#pragma unroll
            for (int c = 0; c < 4; c++) acc[i][j][c] = 0.f;

    auto load_chunk = [&](int ch, int stage) {
        const int k0 = ch * BK;
        const uint32_t base = sb + stage * STAGE1_BYTES;
#pragma unroll
        for (int i = 0; i < 4; i++) {
            int q = tid + i * 256;
            int row = q >> 3, c = q & 7;
            uint32_t so = sw128(row * 128 + c * 16);
            cp_async16(base + so, A + (size_t)(bm + row) * C_ + k0 + c * 8);
            cp_async16(base + TILE_B + so, W + (size_t)(bn + row) * C_ + k0 + c * 8);
        }
    };

    load_chunk(0, 0); cp_commit();
    load_chunk(1, 1); cp_commit();

    const int lrowA = (lane & 7) + ((lane >> 3) & 1) * 8;
    const int lkbA  = ((lane >> 3) >> 1) * 16;
    const int lrowB = (lane & 7) + ((lane >> 3) >> 1) * 8;
    const int lkbB  = ((lane >> 3) & 1) * 16;

    for (int ch = 0; ch < NCHUNK; ch++) {
        // pending groups here: {ch, ch+1}. Wait to <=1 => group ch complete.
        cp_wait<1>();
        // all warps done reading stage (ch-1) before its buffer is overwritten below
        __syncthreads();
        if (ch + 2 < NCHUNK) { load_chunk(ch + 2, (ch + 2) % STAGES1); cp_commit(); }

        const uint32_t base = sb + (ch % STAGES1) * STAGE1_BYTES;

#pragma unroll
        for (int ks = 0; ks < 4; ks++) {
            uint32_t b[2][4];
#pragma unroll
            for (int nt2 = 0; nt2 < 2; nt2++) {
                int r = wn + nt2 * 16 + lrowB;
                ldmatrix4(b[nt2][0], b[nt2][1], b[nt2][2], b[nt2][3],
                          base + TILE_B + sw128(r * 128 + ks * 32 + lkbB));
            }
            uint32_t a[4][4];
#pragma unroll
            for (int mt = 0; mt < 4; mt++) {
                int r = wm + mt * 16 + lrowA;
                ldmatrix4(a[mt][0], a[mt][1], a[mt][2], a[mt][3],
                          base + sw128(r * 128 + ks * 32 + lkbA));
            }
#pragma unroll
            for (int mt = 0; mt < 4; mt++)
#pragma unroll
                for (int nt = 0; nt < 4; nt++)
                    mma16816(acc[mt][nt][0], acc[mt][nt][1], acc[mt][nt][2], acc[mt][nt][3],
                             a[mt][0], a[mt][1], a[mt][2], a[mt][3],
                             b[nt >> 1][(nt & 1) * 2 + 0], b[nt >> 1][(nt & 1) * 2 + 1]);
        }
    }

#pragma unroll
    for (int mt = 0; mt < 4; mt++) {
        int row0 = bm + wm + mt * 16 + (lane >> 2);
#pragma unroll
        for (int nt = 0; nt < 4; nt++) {
            int col = bn + wn + nt * 8 + (lane & 3) * 2;
            *(float2*)(Out + (size_t)row0 * C_ + col)       = make_float2(acc[mt][nt][0], acc[mt][nt][1]);
            *(float2*)(Out + (size_t)(row0 + 8) * C_ + col) = make_float2(acc[mt][nt][2], acc[mt][nt][3]);
        }
    }
}

// ---------------- fp32 -> fp16 hi/lo split ----------------
__global__ __launch_bounds__(256)
void split_fp16(const float* __restrict__ in, __half* __restrict__ hi,
                __half* __restrict__ lo, int n4)
{
    int i = blockIdx.x * blockDim.x + threadIdx.x;
    if (i >= n4) return;
    float4 v = ((const float4*)in)[i];
    __half h0 = __float2half_rn(v.x), h1 = __float2half_rn(v.y);
    __half h2 = __float2half_rn(v.z), h3 = __float2half_rn(v.w);
    __half2 hp0{h0, h1}, hp1{h2, h3};
    __half2 lp0{__float2half_rn(v.x - __half2float(h0)), __float2half_rn(v.y - __half2float(h1))};
    __half2 lp1{__float2half_rn(v.z - __half2float(h2)), __float2half_rn(v.w - __half2float(h3))};
    ((__half2*)hi)[i * 2 + 0] = hp0;
    ((__half2*)hi)[i * 2 + 1] = hp1;
    ((__half2*)lo)[i * 2 + 0] = lp0;
    ((__half2*)lo)[i * 2 + 1] = lp1;
}

__global__ __launch_bounds__(256)
void conv_fp16x3(const float* __restrict__ i0, const float* __restrict__ i1,
                 const float* __restrict__ i2, __half* __restrict__ o0,
                 __half* __restrict__ o1, __half* __restrict__ o2, int n4each)
{
    int i = blockIdx.x * blockDim.x + threadIdx.x;
    int which = i / n4each;
    int j = i - which * n4each;
    const float* in = (which == 0) ? i0 : (which == 1) ? i1 : i2;
    __half* out = (which == 0) ? o0 : (which == 1) ? o1 : o2;
    float4 v = ((const float4*)in)[j];
    __half2 p0{__float2half_rn(v.x), __float2half_rn(v.y)};
    __half2 p1{__float2half_rn(v.z), __float2half_rn(v.w)};
    ((__half2*)out)[j * 2 + 0] = p0;
    ((__half2*)out)[j * 2 + 1] = p1;
}

// ---------------- segment-parallel WKV scan (hi-only output) ----------------
#define SEG 8
#define LSEG (T_ / SEG)   // 128

__global__ __launch_bounds__(256)
void wkv_scan_seg(const float* __restrict__ time_decay,
                  const float* __restrict__ time_first)
{
    __shared__ float s_a[SEG][32], s_b[SEG][32], s_p[SEG][32];

    const int lane = threadIdx.x & 31;
    const int seg  = threadIdx.x >> 5;
    const int b  = blockIdx.x >> 5;
    const int c  = ((blockIdx.x & 31) << 5) + lane;

    const float w = -__expf(time_decay[c]);
    const float u = time_first[c];

    const size_t off = ((size_t)b * T_ + (size_t)seg * LSEG) * C_ + c;
    const float* kp = g_k + off;
    const float* rp = g_r + off;

    // phase 1: local state-only scan, zero init
    float a = 0.f, bd = 0.f, pp = -1e38f;
#pragma unroll 4
    for (int t = 0; t < LSEG; t++) {
        const float kt = kp[(size_t)t * C_];
        const float vt = rp[(size_t)t * C_];
        float ww2 = pp + w;
        float d2  = ww2 - kt;
        float eb  = __expf(-fabsf(d2));
        float e1b = (d2 >= 0.f) ? 1.f : eb;
        float e2b = (d2 >= 0.f) ? eb : 1.f;
        a  = e1b * a + e2b * vt;
        bd = e1b * bd + e2b;
        pp = fmaxf(ww2, kt);
    }
    s_a[seg][lane] = a; s_b[seg][lane] = bd; s_p[seg][lane] = pp;
    __syncthreads();

    // phase 2: prefix over segments 0..seg-1 (pass-through decay exp(L*w))
    float a0 = 0.f, b0 = 0.f, p0 = -1e38f;
    const float Lw = (float)LSEG * w;
    for (int j = 0; j < seg; j++) {
        float aj = s_a[j][lane], bj = s_b[j][lane], pj = s_p[j][lane];
        float pd = p0 + Lw;
        float pn = fmaxf(pd, pj);
        float ea = __expf(pd - pn);
        float ej = __expf(pj - pn);
        a0 = ea * a0 + ej * aj;
        b0 = ea * b0 + ej * bj;
        p0 = pn;
    }

    // phase 3: re-scan with incoming state, emit sigmoid(r)*y in fp16
    a = a0; bd = b0; pp = p0;
    __half* shp = g_sh + off;
#pragma unroll 4
    for (int t = 0; t < LSEG; t++) {
        const float kt = kp[(size_t)t * C_];
        const float rt = rp[(size_t)t * C_];
        const float vt = rt;

        float ww = u + kt;
        float d  = pp - ww;
        float e  = __expf(-fabsf(d));
        float e1 = (d >= 0.f) ? 1.f : e;
        float e2 = (d >= 0.f) ? e : 1.f;
        float y  = __fdividef(e1 * a + e2 * vt, e1 * bd + e2);

        float ww2 = pp + w;
        float d2  = ww2 - kt;
        float ebv = __expf(-fabsf(d2));
        float e1b = (d2 >= 0.f) ? 1.f : ebv;
        float e2b = (d2 >= 0.f) ? ebv : 1.f;
        a  = e1b * a + e2b * vt;
        bd = e1b * bd + e2b;
        pp = fmaxf(ww2, kt);

        float sig = __fdividef(1.f, 1.f + __expf(-rt));
        shp[(size_t)t * C_] = __float2half_rn(sig * y);
    }
}

// ---------------- launch ----------------
extern "C" void kernel_launch(void* const* d_in, const int* in_sizes, int n_in,
                              void* d_out, int out_size)
{
    const float* x  = (const float*)d_in[0];
    const float* Wk = (const float*)d_in[1];
    const float* Wr = (const float*)d_in[2];
    const float* Wo = (const float*)d_in[3];
    const float* td = (const float*)d_in[4];
    const float* tf = (const float*)d_in[5];
    float* out = (float*)d_out;

    __half *xh, *xl, *wk, *wr, *wo, *sh;
    float *gk, *gr;
    cudaGetSymbolAddress((void**)&xh, g_xh); cudaGetSymbolAddress((void**)&xl, g_xl);
    cudaGetSymbolAddress((void**)&wk, g_wk); cudaGetSymbolAddress((void**)&wr, g_wr);
    cudaGetSymbolAddress((void**)&wo, g_wo);
    cudaGetSymbolAddress((void**)&sh, g_sh);
    cudaGetSymbolAddress((void**)&gk, g_k);  cudaGetSymbolAddress((void**)&gr, g_r);

    cudaFuncSetAttribute(gemm_fp16x2, cudaFuncAttributeMaxDynamicSharedMemorySize, SMEM_GEMM2);
    cudaFuncSetAttribute(gemm_fp16x1, cudaFuncAttributeMaxDynamicSharedMemorySize, SMEM_GEMM1);

    split_fp16<<<(M_ * C_ / 4 + 255) / 256, 256>>>(x, xh, xl, M_ * C_ / 4);
    conv_fp16x3<<<(3 * C_ * C_ / 4 + 255) / 256, 256>>>(Wk, Wr, Wo, wk, wr, wo, C_ * C_ / 4);

    dim3 grid(C_ / BN, M_ / BM);   // (8, 128)
    gemm_fp16x2<<<grid, 256, SMEM_GEMM2>>>(xh, xl, wk, gk);
    gemm_fp16x2<<<grid, 256, SMEM_GEMM2>>>(xh, xl, wr, gr);
    wkv_scan_seg<<<(B_ * C_) / 32, 256>>>(td, tf);
    gemm_fp16x1<<<grid, 256, SMEM_GEMM1>>>(sh, wo, out);
}

// round 14
// speedup vs baseline: 1.6470x; 1.3114x over previous
#include <cuda_runtime.h>
#include <cuda_fp16.h>
#include <cstdint>

#define B_  16
#define T_  1024
#define C_  1024
#define M_  (B_ * T_)   // 16384

// ---------------- scratch ----------------
__device__ __half g_xh[M_ * C_];
__device__ __half g_wk[C_ * C_];
__device__ __half g_wr[C_ * C_];
__device__ __half g_wo[C_ * C_];
__device__ float g_k[M_ * C_];
__device__ float g_r[M_ * C_];
__device__ __half g_sh[M_ * C_];

// ---------------- helpers ----------------
__device__ __forceinline__ uint32_t smem_u32(const void* p) {
    uint32_t a;
    asm("{ .reg .u64 t; cvta.to.shared.u64 t, %1; cvt.u32.u64 %0, t; }" : "=r"(a) : "l"(p));
    return a;
}
__device__ __forceinline__ void cp_async16(uint32_t s, const void* g) {
    asm volatile("cp.async.cg.shared.global [%0], [%1], 16;" :: "r"(s), "l"(g) : "memory");
}
__device__ __forceinline__ void cp_commit() {
    asm volatile("cp.async.commit_group;" ::: "memory");
}
template<int N> __device__ __forceinline__ void cp_wait() {
    asm volatile("cp.async.wait_group %0;" :: "n"(N) : "memory");
}
__device__ __forceinline__ void ldmatrix4(uint32_t& r0, uint32_t& r1, uint32_t& r2, uint32_t& r3, uint32_t addr) {
    asm volatile("ldmatrix.sync.aligned.m8n8.x4.shared.b16 {%0,%1,%2,%3}, [%4];"
                 : "=r"(r0), "=r"(r1), "=r"(r2), "=r"(r3) : "r"(addr));
}
__device__ __forceinline__ void mma16816(float& c0, float& c1, float& c2, float& c3,
                                         uint32_t a0, uint32_t a1, uint32_t a2, uint32_t a3,
                                         uint32_t b0, uint32_t b1) {
    asm volatile("mma.sync.aligned.m16n8k16.row.col.f32.f16.f16.f32 "
                 "{%0,%1,%2,%3}, {%4,%5,%6,%7}, {%8,%9}, {%0,%1,%2,%3};"
                 : "+f"(c0), "+f"(c1), "+f"(c2), "+f"(c3)
                 : "r"(a0), "r"(a1), "r"(a2), "r"(a3), "r"(b0), "r"(b1));
}
__device__ __forceinline__ uint32_t sw128(uint32_t o) { return o ^ ((o >> 3) & 0x70); }

#define BM 128
#define BN 128
#define BK 64
#define NCHUNK (C_ / BK)                    // 16
#define TILE_B (128 * 128)                  // 16KB

// ---------------- fp16 single-term GEMM (NT): Out = A @ W^T, 3-stage ----------------
#define STAGE1_BYTES (2 * TILE_B)            // 32KB
#define STAGES1 3
#define SMEM_GEMM1 (STAGES1 * STAGE1_BYTES)  // 96KB

__global__ __launch_bounds__(256, 2)
void gemm_fp16x1(const __half* __restrict__ A, const __half* __restrict__ W,
                 float* __restrict__ Out)
{
    extern __shared__ char smem[];
    const uint32_t sb = smem_u32(smem);
    const int tid = threadIdx.x;
    const int wid = tid >> 5;
    const int lane = tid & 31;
    const int bm = blockIdx.y * BM;
    const int bn = blockIdx.x * BN;

    const int wm = (wid >> 2) * 64;
    const int wn = (wid & 3) * 32;

    float acc[4][4][4];
#pragma unroll
    for (int i = 0; i < 4; i++)
#pragma unroll
        for (int j = 0; j < 4; j++)
#pragma unroll
            for (int c = 0; c < 4; c++) acc[i][j][c] = 0.f;

    auto load_chunk = [&](int ch, int stage) {
        const int k0 = ch * BK;
        const uint32_t base = sb + stage * STAGE1_BYTES;
#pragma unroll
        for (int i = 0; i < 4; i++) {
            int q = tid + i * 256;
            int row = q >> 3, c = q & 7;
            uint32_t so = sw128(row * 128 + c * 16);
            cp_async16(base + so, A + (size_t)(bm + row) * C_ + k0 + c * 8);
            cp_async16(base + TILE_B + so, W + (size_t)(bn + row) * C_ + k0 + c * 8);
        }
    };

    load_chunk(0, 0); cp_commit();
    load_chunk(1, 1); cp_commit();

    const int lrowA = (lane & 7) + ((lane >> 3) & 1) * 8;
    const int lkbA  = ((lane >> 3) >> 1) * 16;
    const int lrowB = (lane & 7) + ((lane >> 3) >> 1) * 8;
    const int lkbB  = ((lane >> 3) & 1) * 16;

    for (int ch = 0; ch < NCHUNK; ch++) {
        // pending: {ch, ch+1} except at the tail. Ensure chunk ch is complete.
        if (ch + 1 < NCHUNK) cp_wait<1>(); else cp_wait<0>();
        // all warps done reading stage (ch-1) before its buffer is overwritten
        __syncthreads();
        if (ch + 2 < NCHUNK) { load_chunk(ch + 2, (ch + 2) % STAGES1); cp_commit(); }

        const uint32_t base = sb + (ch % STAGES1) * STAGE1_BYTES;

#pragma unroll
        for (int ks = 0; ks < 4; ks++) {
            uint32_t b[2][4];
#pragma unroll
            for (int nt2 = 0; nt2 < 2; nt2++) {
                int r = wn + nt2 * 16 + lrowB;
                ldmatrix4(b[nt2][0], b[nt2][1], b[nt2][2], b[nt2][3],
                          base + TILE_B + sw128(r * 128 + ks * 32 + lkbB));
            }
            uint32_t a[4][4];
#pragma unroll
            for (int mt = 0; mt < 4; mt++) {
                int r = wm + mt * 16 + lrowA;
                ldmatrix4(a[mt][0], a[mt][1], a[mt][2], a[mt][3],
                          base + sw128(r * 128 + ks * 32 + lkbA));
            }
#pragma unroll
            for (int mt = 0; mt < 4; mt++)
#pragma unroll
                for (int nt = 0; nt < 4; nt++)
                    mma16816(acc[mt][nt][0], acc[mt][nt][1], acc[mt][nt][2], acc[mt][nt][3],
                             a[mt][0], a[mt][1], a[mt][2], a[mt][3],
                             b[nt >> 1][(nt & 1) * 2 + 0], b[nt >> 1][(nt & 1) * 2 + 1]);
        }
    }

#pragma unroll
    for (int mt = 0; mt < 4; mt++) {
        int row0 = bm + wm + mt * 16 + (lane >> 2);
#pragma unroll
        for (int nt = 0; nt < 4; nt++) {
            int col = bn + wn + nt * 8 + (lane & 3) * 2;
            *(float2*)(Out + (size_t)row0 * C_ + col)       = make_float2(acc[mt][nt][0], acc[mt][nt][1]);
            *(float2*)(Out + (size_t)(row0 + 8) * C_ + col) = make_float2(acc[mt][nt][2], acc[mt][nt][3]);
        }
    }
}

// ---------------- fp32 -> fp16 convert (x) ----------------
__global__ __launch_bounds__(256)
void conv_fp16(const float* __restrict__ in, __half* __restrict__ out, int n4)
{
    int i = blockIdx.x * blockDim.x + threadIdx.x;
    if (i >= n4) return;
    float4 v = ((const float4*)in)[i];
    __half2 p0{__float2half_rn(v.x), __float2half_rn(v.y)};
    __half2 p1{__float2half_rn(v.z), __float2half_rn(v.w)};
    ((__half2*)out)[i * 2 + 0] = p0;
    ((__half2*)out)[i * 2 + 1] = p1;
}

// all 3 weight conversions in one launch
__global__ __launch_bounds__(256)
void conv_fp16x3(const float* __restrict__ i0, const float* __restrict__ i1,
                 const float* __restrict__ i2, __half* __restrict__ o0,
                 __half* __restrict__ o1, __half* __restrict__ o2, int n4each)
{
    int i = blockIdx.x * blockDim.x + threadIdx.x;
    int which = i / n4each;
    int j = i - which * n4each;
    const float* in = (which == 0) ? i0 : (which == 1) ? i1 : i2;
    __half* out = (which == 0) ? o0 : (which == 1) ? o1 : o2;
    float4 v = ((const float4*)in)[j];
    __half2 p0{__float2half_rn(v.x), __float2half_rn(v.y)};
    __half2 p1{__float2half_rn(v.z), __float2half_rn(v.w)};
    ((__half2*)out)[j * 2 + 0] = p0;
    ((__half2*)out)[j * 2 + 1] = p1;
}

// ---------------- segment-parallel WKV scan (unchanged from R12) ----------------
#define SEG 8
#define LSEG (T_ / SEG)   // 128

__global__ __launch_bounds__(256)
void wkv_scan_seg(const float* __restrict__ time_decay,
                  const float* __restrict__ time_first)
{
    __shared__ float s_a[SEG][32], s_b[SEG][32], s_p[SEG][32];

    const int lane = threadIdx.x & 31;
    const int seg  = threadIdx.x >> 5;
    const int b  = blockIdx.x >> 5;
    const int c  = ((blockIdx.x & 31) << 5) + lane;

    const float w = -__expf(time_decay[c]);
    const float u = time_first[c];

    const size_t off = ((size_t)b * T_ + (size_t)seg * LSEG) * C_ + c;
    const float* kp = g_k + off;
    const float* rp = g_r + off;

    // phase 1: local state-only scan, zero init
    float a = 0.f, bd = 0.f, pp = -1e38f;
#pragma unroll 4
    for (int t = 0; t < LSEG; t++) {
        const float kt = kp[(size_t)t * C_];
        const float vt = rp[(size_t)t * C_];
        float ww2 = pp + w;
        float d2  = ww2 - kt;
        float eb  = __expf(-fabsf(d2));
        float e1b = (d2 >= 0.f) ? 1.f : eb;
        float e2b = (d2 >= 0.f) ? eb : 1.f;
        a  = e1b * a + e2b * vt;
        bd = e1b * bd + e2b;
        pp = fmaxf(ww2, kt);
    }
    s_a[seg][lane] = a; s_b[seg][lane] = bd; s_p[seg][lane] = pp;
    __syncthreads();

    // phase 2: prefix over segments 0..seg-1 (pass-through decay exp(L*w))
    float a0 = 0.f, b0 = 0.f, p0 = -1e38f;
    const float Lw = (float)LSEG * w;
    for (int j = 0; j < seg; j++) {
        float aj = s_a[j][lane], bj = s_b[j][lane], pj = s_p[j][lane];
        float pd = p0 + Lw;
        float pn = fmaxf(pd, pj);
        float ea = __expf(pd - pn);
        float ej = __expf(pj - pn);
        a0 = ea * a0 + ej * aj;
        b0 = ea * b0 + ej * bj;
        p0 = pn;
    }

    // phase 3: re-scan with incoming state, emit sigmoid(r)*y in fp16
    a = a0; bd = b0; pp = p0;
    __half* shp = g_sh + off;
#pragma unroll 4
    for (int t = 0; t < LSEG; t++) {
        const float kt = kp[(size_t)t * C_];
        const float rt = rp[(size_t)t * C_];
        const float vt = rt;

        float ww = u + kt;
        float d  = pp - ww;
        float e  = __expf(-fabsf(d));
        float e1 = (d >= 0.f) ? 1.f : e;
        float e2 = (d >= 0.f) ? e : 1.f;
        float y  = __fdividef(e1 * a + e2 * vt, e1 * bd + e2);

        float ww2 = pp + w;
        float d2  = ww2 - kt;
        float ebv = __expf(-fabsf(d2));
        float e1b = (d2 >= 0.f) ? 1.f : ebv;
        float e2b = (d2 >= 0.f) ? ebv : 1.f;
        a  = e1b * a + e2b * vt;
        bd = e1b * bd + e2b;
        pp = fmaxf(ww2, kt);

        float sig = __fdividef(1.f, 1.f + __expf(-rt));
        shp[(size_t)t * C_] = __float2half_rn(sig * y);
    }
}

// ---------------- launch ----------------
extern "C" void kernel_launch(void* const* d_in, const int* in_sizes, int n_in,
                              void* d_out, int out_size)
{
    const float* x  = (const float*)d_in[0];
    const float* Wk = (const float*)d_in[1];
    const float* Wr = (const float*)d_in[2];
    const float* Wo = (const float*)d_in[3];
    const float* td = (const float*)d_in[4];
    const float* tf = (const float*)d_in[5];
    float* out = (float*)d_out;

    __half *xh, *wk, *wr, *wo, *sh;
    float *gk, *gr;
    cudaGetSymbolAddress((void**)&xh, g_xh);
    cudaGetSymbolAddress((void**)&wk, g_wk); cudaGetSymbolAddress((void**)&wr, g_wr);
    cudaGetSymbolAddress((void**)&wo, g_wo);
    cudaGetSymbolAddress((void**)&sh, g_sh);
    cudaGetSymbolAddress((void**)&gk, g_k);  cudaGetSymbolAddress((void**)&gr, g_r);

    cudaFuncSetAttribute(gemm_fp16x1, cudaFuncAttributeMaxDynamicSharedMemorySize, SMEM_GEMM1);

    conv_fp16<<<(M_ * C_ / 4 + 255) / 256, 256>>>(x, xh, M_ * C_ / 4);
    conv_fp16x3<<<(3 * C_ * C_ / 4 + 255) / 256, 256>>>(Wk, Wr, Wo, wk, wr, wo, C_ * C_ / 4);

    dim3 grid(C_ / BN, M_ / BM);   // (8, 128)
    gemm_fp16x1<<<grid, 256, SMEM_GEMM1>>>(xh, wk, gk);
    gemm_fp16x1<<<grid, 256, SMEM_GEMM1>>>(xh, wr, gr);
    wkv_scan_seg<<<(B_ * C_) / 32, 256>>>(td, tf);
    gemm_fp16x1<<<grid, 256, SMEM_GEMM1>>>(sh, wo, out);
}